// round 14
// baseline (speedup 1.0000x reference)
#include <cuda_runtime.h>
#include <cstdint>

// Problem constants (fixed shapes per reference)
#define B_DIM 4
#define P_DIM 2
#define T_DIM 1024
#define F_DIM 1024
#define D_DIM 16
#define CHUNK 128
#define NCHUNK (F_DIM / CHUNK)   // 8
#define T_PER_BLOCK 8

// Per-(b,d,chunk) integer shifts. 4*16*8 = 512 ints.
__device__ int g_shift[B_DIM * D_DIM * NCHUNK];

// ---------------------------------------------------------------------------
// Kernel 1 (minimal): one block, 512 threads; thread (bd, c) runs the
// sequential rounded-product chain that exactly reproduces the reference's
// trunc(chunk_mean) (rel_err == 0.0 verified with this exact order).
// No smem, no barriers, no other outputs.
// ---------------------------------------------------------------------------
__global__ void dedisp_prep_kernel(const float* __restrict__ dm,
                                   const float* __restrict__ df)
{
    const int idx = threadIdx.x;          // 0..511
    const int bd  = idx >> 3;             // (b*16 + d)
    const int c   = idx & (NCHUNK - 1);   // chunk

    const float dmv = dm[bd];
    const float* base = df + c * CHUNK;

    float sum = 0.0f;
    #pragma unroll 16
    for (int i = 0; i < CHUNK; i++)
        sum = __fadd_rn(sum, __fmul_rn(dmv, base[i]));  // round mul, then add

    const float mean = __fmul_rn(sum, 0.0078125f);       // exact *2^-7
    int s = (int)truncf(mean);
    if (s < 0) s = 0;
    g_shift[idx] = s & (T_DIM - 1);
}

// ---------------------------------------------------------------------------
// Kernel 2: the gather-copy, byte-identical memory behavior to the 83.2us
// R7 kernel (float4 __ldg loads, plain float4 stores).
// grid = B*D*P*(T/T_PER_BLOCK) = 16384 blocks, 256 threads.
// Warp w handles chunk w -> shift is warp-uniform.
// The 64 (p==0, tb==0) blocks additionally write the delays output tail
// (coalesced, independent of g_shift).
// ---------------------------------------------------------------------------
__global__ __launch_bounds__(256)
void dedisp_gather_kernel(const float4* __restrict__ x,
                          float4*       __restrict__ out,
                          const float*  __restrict__ dm,
                          const float*  __restrict__ df,
                          float*        __restrict__ delays)
{
    const int bi = blockIdx.x;
    const int tb = bi & (T_DIM / T_PER_BLOCK - 1);   // 0..127
    const int p  = (bi >> 7) & (P_DIM - 1);
    const int d  = (bi >> 8) & (D_DIM - 1);
    const int b  = bi >> 12;
    const int bd = b * D_DIM + d;

    const int tid = threadIdx.x;          // 0..255, f4 index
    const int c   = tid >> 5;             // chunk = warp id

    // delays tail: 64 blocks, coalesced, no dependency on shifts
    if (p == 0 && tb == 0) {
        const float dmv = dm[bd];
        float* drow = delays + (size_t)bd * F_DIM;
        #pragma unroll
        for (int j = 0; j < 4; j++) {
            const int f = tid + j * 256;
            drow[f] = __fmul_rn(dmv, df[f]);
        }
    }

    const int s = g_shift[bd * NCHUNK + c];

    const int F4 = F_DIM / 4;             // 256 float4 per row

    const float4* __restrict__ xrow =
        x + (size_t)(b * P_DIM + p) * T_DIM * F4;

    float4* __restrict__ orow =
        out + ((size_t)(bd * P_DIM + p) * T_DIM
               + (size_t)tb * T_PER_BLOCK) * F4 + tid;

    const int t0 = tb * T_PER_BLOCK;

    #pragma unroll
    for (int k = 0; k < T_PER_BLOCK; k++) {
        int ts = t0 + k + s;
        if (ts >= T_DIM) ts -= T_DIM;     // s < 1024, t < 1024 -> one subtract
        orow[k * F4] = __ldg(&xrow[(size_t)ts * F4 + tid]);
    }
}

// ---------------------------------------------------------------------------
// Launch: two plain sequential graph nodes (no PDL, no device-side sync).
// ---------------------------------------------------------------------------
extern "C" void kernel_launch(void* const* d_in, const int* in_sizes, int n_in,
                              void* d_out, int out_size)
{
    const float* x  = (const float*)d_in[0];   // (4,2,1024,1024)
    const float* dm = (const float*)d_in[1];   // (4,16)
    const float* df = (const float*)d_in[2];   // (1024,)

    float* out = (float*)d_out;
    // Output layout: dedispersed (4,16,2,1024,1024) then delays (4,16,1024)
    float* delays = out + (size_t)B_DIM * D_DIM * P_DIM * T_DIM * F_DIM;

    dedisp_prep_kernel<<<1, 512>>>(dm, df);

    const int nblocks = B_DIM * D_DIM * P_DIM * (T_DIM / T_PER_BLOCK); // 16384
    dedisp_gather_kernel<<<nblocks, 256>>>((const float4*)x, (float4*)out,
                                           dm, df, delays);
}

// round 15
// speedup vs baseline: 1.0884x; 1.0884x over previous
#include <cuda_runtime.h>
#include <cstdint>

// Problem constants (fixed shapes per reference)
#define B_DIM 4
#define P_DIM 2
#define T_DIM 1024
#define F_DIM 1024
#define D_DIM 16
#define CHUNK 128
#define NCHUNK (F_DIM / CHUNK)   // 8
#define T_PER_BLOCK 8

// Per-(b,d,chunk) integer shifts. 4*16*8 = 512 ints.
__device__ int g_shift[B_DIM * D_DIM * NCHUNK];

// ---------------------------------------------------------------------------
// Kernel 1: one block per (bd, chunk) = 512 blocks x 128 threads.
// Each thread computes one rounded product dm*df[f] (fp32, matches reference),
// writes the delays output slice (coalesced), and stages the product in smem.
// Thread 0 then performs the sequential rounded-add chain over the 128 staged
// products -- the exact summation order that verified rel_err == 0.0 --
// followed by trunc/clamp into g_shift.
// ---------------------------------------------------------------------------
__global__ __launch_bounds__(128)
void dedisp_prep_kernel(const float* __restrict__ dm,
                        const float* __restrict__ df,
                        float* __restrict__ delays_out)
{
    const int bd = blockIdx.x >> 3;              // 0..63 : (b*16 + d)
    const int c  = blockIdx.x & (NCHUNK - 1);    // chunk 0..7
    const int t  = threadIdx.x;                  // 0..127

    __shared__ float sh[CHUNK];

    const int f = c * CHUNK + t;
    const float prod = __fmul_rn(dm[bd], df[f]); // round mul (reference order)
    delays_out[(size_t)bd * F_DIM + f] = prod;
    sh[t] = prod;
    __syncthreads();

    if (t == 0) {
        float sum = 0.0f;
        #pragma unroll 16
        for (int i = 0; i < CHUNK; i++)
            sum = __fadd_rn(sum, sh[i]);          // sequential rounded adds
        const float mean = __fmul_rn(sum, 0.0078125f);  // exact *2^-7
        int s = (int)truncf(mean);
        if (s < 0) s = 0;
        g_shift[bd * NCHUNK + c] = s & (T_DIM - 1);
    }
}

// ---------------------------------------------------------------------------
// Kernel 2: the gather-copy -- byte-identical to the proven 83.2us R7 kernel.
// grid = B*D*P*(T/T_PER_BLOCK) = 16384 blocks, 256 threads.
// Warp w handles chunk w -> shift is warp-uniform.
// ---------------------------------------------------------------------------
__global__ __launch_bounds__(256)
void dedisp_gather_kernel(const float4* __restrict__ x,
                          float4* __restrict__ out)
{
    const int bi  = blockIdx.x;
    const int tb  = bi & (T_DIM / T_PER_BLOCK - 1);   // 0..127
    const int p   = (bi >> 7) & (P_DIM - 1);
    const int d   = (bi >> 8) & (D_DIM - 1);
    const int b   = bi >> 12;

    const int tid = threadIdx.x;          // 0..255, f4 index
    const int c   = tid >> 5;             // chunk = warp id

    const int s = g_shift[(b * D_DIM + d) * NCHUNK + c];

    const int F4 = F_DIM / 4;             // 256 float4 per row

    const float4* __restrict__ xrow =
        x + (size_t)(b * P_DIM + p) * T_DIM * F4;

    float4* __restrict__ orow =
        out + ((size_t)((b * D_DIM + d) * P_DIM + p) * T_DIM
               + (size_t)tb * T_PER_BLOCK) * F4 + tid;

    const int t0 = tb * T_PER_BLOCK;

    #pragma unroll
    for (int k = 0; k < T_PER_BLOCK; k++) {
        int ts = t0 + k + s;
        if (ts >= T_DIM) ts -= T_DIM;     // s < 1024, t < 1024 -> one subtract
        orow[k * F4] = __ldg(&xrow[(size_t)ts * F4 + tid]);
    }
}

// ---------------------------------------------------------------------------
// Launch: two plain sequential graph nodes.
// ---------------------------------------------------------------------------
extern "C" void kernel_launch(void* const* d_in, const int* in_sizes, int n_in,
                              void* d_out, int out_size)
{
    const float* x  = (const float*)d_in[0];   // (4,2,1024,1024)
    const float* dm = (const float*)d_in[1];   // (4,16)
    const float* df = (const float*)d_in[2];   // (1024,)

    float* out = (float*)d_out;
    // Output layout: dedispersed (4,16,2,1024,1024) then delays (4,16,1024)
    float* delays = out + (size_t)B_DIM * D_DIM * P_DIM * T_DIM * F_DIM;

    dedisp_prep_kernel<<<B_DIM * D_DIM * NCHUNK, 128>>>(dm, df, delays);

    const int nblocks = B_DIM * D_DIM * P_DIM * (T_DIM / T_PER_BLOCK); // 16384
    dedisp_gather_kernel<<<nblocks, 256>>>((const float4*)x, (float4*)out);
}